// round 16
// baseline (speedup 1.0000x reference)
#include <cuda_runtime.h>
#include <cuda_fp16.h>
#include <math.h>
#include <stdint.h>

#define KC   256
#define D    512
#define NLOW 130816

// Dense L in fp16, natural orientation: g_Lh[k][d][e] = L_k[d][e].
__device__ __half g_Lh[(size_t)KC * D * D];
// X in fp16.
__device__ __half g_Xh[(size_t)1024 * D];
// wL[k][e] = sum_d w_k[d] * Lh_k[d][e]  (fp32)
__device__ float g_wL[(size_t)KC * D];
// Per-e-block partial squared sums: g_part[j][b][k]
__device__ float g_part[(size_t)4 * 1024 * KC];

__device__ __forceinline__ uint32_t smem_u32(const void* p) {
    uint32_t a;
    asm("{ .reg .u64 t; cvta.to.shared.u64 t, %1; cvt.u32.u64 %0, t; }"
        : "=r"(a) : "l"(p));
    return a;
}
__device__ __forceinline__ void cpasync16(uint32_t dst, const void* src) {
    asm volatile("cp.async.cg.shared.global [%0], [%1], 16;"
                 :: "r"(dst), "l"(src) : "memory");
}
#define LDSM4(r0, r1, r2, r3, addr) \
    asm volatile("ldmatrix.sync.aligned.m8n8.x4.shared.b16 {%0,%1,%2,%3}, [%4];" \
                 : "=r"(r0), "=r"(r1), "=r"(r2), "=r"(r3) : "r"(addr))
#define LDSM4T(r0, r1, r2, r3, addr) \
    asm volatile("ldmatrix.sync.aligned.m8n8.x4.trans.shared.b16 {%0,%1,%2,%3}, [%4];" \
                 : "=r"(r0), "=r"(r1), "=r"(r2), "=r"(r3) : "r"(addr))
#define HMMA(acc, a, b0r, b1r) \
    asm volatile( \
        "mma.sync.aligned.m16n8k16.row.col.f32.f16.f16.f32 " \
        "{%0,%1,%2,%3},{%4,%5,%6,%7},{%8,%9},{%0,%1,%2,%3};" \
        : "+f"((acc)[0]), "+f"((acc)[1]), "+f"((acc)[2]), "+f"((acc)[3]) \
        : "r"((a)[0]), "r"((a)[1]), "r"((a)[2]), "r"((a)[3]), \
          "r"(b0r), "r"(b1r))

// ---------------------------------------------------------------------------
// build_Lh v3: 4 e-values/thread. Fast path (quad strictly below diagonal):
// 4 unpredicated SCALAR loads (tril row base is not 16B-aligned; float4
// trapped in R15). Slow path handles diag/zero region with predicates.
// ---------------------------------------------------------------------------
__global__ void __launch_bounds__(256)
build_Lh(const float* __restrict__ diags, const float* __restrict__ lower) {
    const size_t i = (size_t)blockIdx.x * 256 + threadIdx.x;  // KC*D*128
    const int ep = ((int)(i & 127)) << 2;        // e..e+3
    const size_t kd = i >> 7;                    // k*D + d
    const int d  = (int)(kd & 511);
    const int kk = (int)(kd >> 9);
    if (d < ((ep >> 7) << 7)) return;            // never-read region
    const float* rowp = lower + (size_t)kk * NLOW + (((size_t)d * (d - 1)) >> 1);
    uint2 u;
    __half2 h;
    if (ep + 3 < d) {
        // fast path: whole quad strictly below the diagonal (no predication)
        const float v0 = rowp[ep + 0];
        const float v1 = rowp[ep + 1];
        const float v2 = rowp[ep + 2];
        const float v3 = rowp[ep + 3];
        h = __floats2half2_rn(v0, v1); u.x = *(uint32_t*)&h;
        h = __floats2half2_rn(v2, v3); u.y = *(uint32_t*)&h;
    } else {
        float v[4];
#pragma unroll
        for (int t = 0; t < 4; ++t) {
            const int e = ep + t;
            v[t] = (e < d) ? rowp[e] : 0.f;
        }
        if (d >= ep && d < ep + 4) { float t = diags[kd]; v[d - ep] = t * t; }
        h = __floats2half2_rn(v[0], v[1]); u.x = *(uint32_t*)&h;
        h = __floats2half2_rn(v[2], v[3]); u.y = *(uint32_t*)&h;
    }
    *(uint2*)((char*)g_Lh + (kd * D + ep) * 2) = u;
}

// ---------------------------------------------------------------------------
__global__ void __launch_bounds__(256)
build_Xh(const float* __restrict__ X) {
    const int i = (blockIdx.x * 256 + threadIdx.x) * 4;   // 1024*512
    float4 x = *(const float4*)&X[i];
    __half2 h0 = __floats2half2_rn(x.x, x.y);
    __half2 h1 = __floats2half2_rn(x.z, x.w);
    *(uint2*)((char*)g_Xh + i * 2) = make_uint2(*(uint32_t*)&h0, *(uint32_t*)&h1);
}

// ---------------------------------------------------------------------------
__global__ void __launch_bounds__(512)
build_wL(const float* __restrict__ W) {
    __shared__ float ws[512];
    const int k = blockIdx.x, e = threadIdx.x;
    ws[e] = W[(size_t)k * D + e];
    __syncthreads();
    const __half* Lk = g_Lh + (size_t)k * D * D;
    float s = 0.f;
    const int dstart = (e >> 7) << 7;
#pragma unroll 4
    for (int d = dstart; d < D; ++d)
        s += ws[d] * __half2float(Lk[(size_t)d * D + e]);
    g_wL[(size_t)k * D + e] = s;
}

// ---------------------------------------------------------------------------
// Main GEMM: Q = Xh @ Lh block; epilogue squares (Q - wL[e]) and row-reduces.
// K-chunks of 64, 3 SMEM stages, one cp.async group per chunk, wait_group 1.
// A stage: 128x64 halfs stride 144 B; B stage: 64x128 halfs stride 272 B.
// Triangular skips: whole-chunk (n0=64, c=0) + fine-grained diagonal chunk
// (c == n0/64): keep only nt < 2ks+2 (B col-blocks at/below the diagonal).
// ---------------------------------------------------------------------------
#define ROFF   0
#define WLOFF  2048
#define STG0   2560
#define ASZ    18432                          /* 128 * 144 */
#define BSZ    17408                          /* 64 * 272 */
#define STGSZ  (ASZ + BSZ)                    /* 35840 */
#define SMEMSZ (2560 + 3 * 35840)             /* 110080 */

__global__ void __launch_bounds__(256, 2)
gml2_mma() {
    extern __shared__ char smem[];
    const int tid = threadIdx.x;
    const int wid = tid >> 5, lid = tid & 31;
    const int b0 = blockIdx.x * 128;
    const int k  = blockIdx.y;
    const int j  = blockIdx.z;
    const int e0 = j << 7;
    const int nc = 8 - (j << 1);              // K-chunks of 64: d in [e0, 512)

    const uint32_t sbase = smem_u32(smem);
    float* wLs = (float*)(smem + WLOFF);
    if (tid < 128) wLs[tid] = g_wL[(size_t)k * D + e0 + tid];

    const __half* Bk = g_Lh + (size_t)k * D * D;   // [d][e]
    const __half* Ab = g_Xh + (size_t)b0 * D;

#define ISSUE_CHUNK(cc, st) do {                                            \
        const int d0_ = e0 + (cc) * 64;                                     \
        const uint32_t as_ = sbase + STG0 + (st) * STGSZ;                   \
        const uint32_t bs_ = as_ + ASZ;                                     \
        _Pragma("unroll")                                                   \
        for (int it = 0; it < 4; ++it) {  /* A: 128 rows x 8 segs */        \
            const int idx = it * 256 + tid;                                 \
            const int row = idx >> 3, seg = idx & 7;                        \
            cpasync16(as_ + row * 144 + seg * 16,                           \
                      Ab + (size_t)row * D + d0_ + seg * 8);                \
        }                                                                   \
        _Pragma("unroll")                                                   \
        for (int it = 0; it < 4; ++it) {  /* B: 64 rows x 16 segs */        \
            const int idx = it * 256 + tid;                                 \
            const int rl = idx >> 4, seg = idx & 15;                        \
            cpasync16(bs_ + rl * 272 + seg * 16,                            \
                      Bk + (size_t)(d0_ + rl) * D + e0 + seg * 8);          \
        }                                                                   \
    } while (0)

    // ---- prologue: issue chunks 0,1
    ISSUE_CHUNK(0, 0);
    asm volatile("cp.async.commit_group;" ::: "memory");
    if (nc > 1) ISSUE_CHUNK(1, 1);
    asm volatile("cp.async.commit_group;" ::: "memory");

    float acc[2][8][4];
#pragma unroll
    for (int mt = 0; mt < 2; ++mt)
#pragma unroll
        for (int nt = 0; nt < 8; ++nt)
#pragma unroll
            for (int q = 0; q < 4; ++q) acc[mt][nt][q] = 0.f;

    const int m0 = (wid & 3) * 32, n0 = (wid >> 2) * 64;
    const int dc = n0 >> 6;                   // this warp's diagonal chunk
    const uint32_t aL = sbase + STG0 + (m0 + (lid & 15)) * 144 + (lid >> 4) * 16;
    const uint32_t bL = sbase + STG0 + ASZ +
                        (lid & 15) * 272 + (lid >> 4) * 16 + n0 * 2;

    int st = 0;
    for (int c = 0; c < nc; ++c) {
        asm volatile("cp.async.wait_group 1;" ::: "memory");
        __syncthreads();

        if (c + 2 < nc) {
            const int st2 = (st + 2 >= 3) ? st - 1 : st + 2;
            ISSUE_CHUNK(c + 2, st2);
        }
        asm volatile("cp.async.commit_group;" ::: "memory");

        const uint32_t aB = aL + st * STGSZ;
        const uint32_t bB = bL + st * STGSZ;

        if (c == dc) {
            // ---- diagonal chunk: cols strictly above diag are zero;
            //      keep nt < 2ks+2 only.
#pragma unroll
            for (int ks = 0; ks < 4; ++ks) {
                uint32_t a[2][4], b[8][2];
#pragma unroll
                for (int mt = 0; mt < 2; ++mt)
                    LDSM4(a[mt][0], a[mt][1], a[mt][2], a[mt][3],
                          aB + mt * (16 * 144) + ks * 32);
#pragma unroll
                for (int nt2 = 0; nt2 <= ks; ++nt2)
                    LDSM4T(b[nt2 * 2][0], b[nt2 * 2][1],
                           b[nt2 * 2 + 1][0], b[nt2 * 2 + 1][1],
                           bB + ks * (16 * 272) + nt2 * 32);
#pragma unroll
                for (int mt = 0; mt < 2; ++mt)
#pragma unroll
                    for (int nt = 0; nt < 8; ++nt)
                        if (nt < 2 * ks + 2)
                            HMMA(acc[mt][nt], a[mt], b[nt][0], b[nt][1]);
            }
        } else if (!(n0 == 64 && c == 0)) {
            // ---- full chunk
#pragma unroll
            for (int ks = 0; ks < 4; ++ks) {
                uint32_t a[2][4], b[8][2];
#pragma unroll
                for (int mt = 0; mt < 2; ++mt)
                    LDSM4(a[mt][0], a[mt][1], a[mt][2], a[mt][3],
                          aB + mt * (16 * 144) + ks * 32);
#pragma unroll
                for (int nt2 = 0; nt2 < 4; ++nt2)
                    LDSM4T(b[nt2 * 2][0], b[nt2 * 2][1],
                           b[nt2 * 2 + 1][0], b[nt2 * 2 + 1][1],
                           bB + ks * (16 * 272) + nt2 * 32);
#pragma unroll
                for (int mt = 0; mt < 2; ++mt)
#pragma unroll
                    for (int nt = 0; nt < 8; ++nt)
                        HMMA(acc[mt][nt], a[mt], b[nt][0], b[nt][1]);
            }
        }
        st = (st == 2) ? 0 : st + 1;
    }
#undef ISSUE_CHUNK

    // ---- epilogue: subtract wL, square, row-reduce
    const int gq = lid >> 2, tg = lid & 3;
    float q[4];
#pragma unroll
    for (int mt = 0; mt < 2; ++mt) {
        float s0 = 0.f, s1 = 0.f;
#pragma unroll
        for (int nt = 0; nt < 8; ++nt) {
            const int c0 = n0 + nt * 8 + tg * 2;
            const float wl0 = wLs[c0], wl1 = wLs[c0 + 1];
            float p0 = acc[mt][nt][0] - wl0;
            float p1 = acc[mt][nt][1] - wl1;
            float p2 = acc[mt][nt][2] - wl0;
            float p3 = acc[mt][nt][3] - wl1;
            s0 += p0 * p0 + p1 * p1;
            s1 += p2 * p2 + p3 * p3;
        }
        q[mt * 2 + 0] = s0;   // row m0 + 16*mt + gq
        q[mt * 2 + 1] = s1;   // row m0 + 16*mt + gq + 8
    }
#pragma unroll
    for (int i = 0; i < 4; ++i) {
        q[i] += __shfl_xor_sync(0xffffffffu, q[i], 1);
        q[i] += __shfl_xor_sync(0xffffffffu, q[i], 2);
    }
    float* red = (float*)(smem + ROFF);
    __syncthreads();
    if (tg == 0) {
        const int wn = wid >> 2;
        const int rr = m0 + gq;
        red[wn * 128 + rr +  0] = q[0];
        red[wn * 128 + rr +  8] = q[1];
        red[wn * 128 + rr + 16] = q[2];
        red[wn * 128 + rr + 24] = q[3];
    }
    __syncthreads();
    if (tid < 128) {
        float s = red[tid] + red[128 + tid];
        g_part[((size_t)j * 1024 + b0 + tid) * KC + k] = s;
    }
}

// ---------------------------------------------------------------------------
__global__ void finalize(float* __restrict__ out) {
    const size_t idx = (size_t)blockIdx.x * 256 + threadIdx.x;  // 1024*256
    float s = g_part[idx] + g_part[262144 + idx] +
              g_part[2 * 262144 + idx] + g_part[3 * 262144 + idx];
    out[idx] = sqrtf(s);
}

// ---------------------------------------------------------------------------
extern "C" void kernel_launch(void* const* d_in, const int* in_sizes, int n_in,
                              void* d_out, int out_size) {
    const float* X     = (const float*)d_in[0];  // [1024, 512]
    const float* W     = (const float*)d_in[1];  // [256, 1, 512]
    const float* diags = (const float*)d_in[2];  // [256, 512]
    const float* lower = (const float*)d_in[3];  // [256, 130816]
    float* out = (float*)d_out;                  // [1024, 256]

    build_Lh<<<(KC * D * 128) / 256, 256>>>(diags, lower);
    build_Xh<<<(1024 * D / 4) / 256, 256>>>(X);
    build_wL<<<KC, 512>>>(W);

    cudaFuncSetAttribute(gml2_mma, cudaFuncAttributeMaxDynamicSharedMemorySize,
                         SMEMSZ);
    dim3 grid(8, KC, 4);
    gml2_mma<<<grid, 256, SMEMSZ>>>();

    finalize<<<1024, 256>>>(out);
}

// round 17
// speedup vs baseline: 1.0365x; 1.0365x over previous
#include <cuda_runtime.h>
#include <cuda_fp16.h>
#include <math.h>
#include <stdint.h>

#define KC   256
#define D    512
#define NLOW 130816

// Dense L in fp16, natural orientation: g_Lh[k][d][e] = L_k[d][e].
__device__ __half g_Lh[(size_t)KC * D * D];
// X in fp16.
__device__ __half g_Xh[(size_t)1024 * D];
// wL[k][e] = sum_d w_k[d] * Lh_k[d][e]  (fp32)
__device__ float g_wL[(size_t)KC * D];
// Per-e-block partial squared sums: g_part[j][b][k]
__device__ float g_part[(size_t)4 * 1024 * KC];

__device__ __forceinline__ uint32_t smem_u32(const void* p) {
    uint32_t a;
    asm("{ .reg .u64 t; cvta.to.shared.u64 t, %1; cvt.u32.u64 %0, t; }"
        : "=r"(a) : "l"(p));
    return a;
}
__device__ __forceinline__ void cpasync16(uint32_t dst, const void* src) {
    asm volatile("cp.async.cg.shared.global [%0], [%1], 16;"
                 :: "r"(dst), "l"(src) : "memory");
}
#define LDSM4(r0, r1, r2, r3, addr) \
    asm volatile("ldmatrix.sync.aligned.m8n8.x4.shared.b16 {%0,%1,%2,%3}, [%4];" \
                 : "=r"(r0), "=r"(r1), "=r"(r2), "=r"(r3) : "r"(addr))
#define LDSM4T(r0, r1, r2, r3, addr) \
    asm volatile("ldmatrix.sync.aligned.m8n8.x4.trans.shared.b16 {%0,%1,%2,%3}, [%4];" \
                 : "=r"(r0), "=r"(r1), "=r"(r2), "=r"(r3) : "r"(addr))
#define HMMA(acc, a, b0r, b1r) \
    asm volatile( \
        "mma.sync.aligned.m16n8k16.row.col.f32.f16.f16.f32 " \
        "{%0,%1,%2,%3},{%4,%5,%6,%7},{%8,%9},{%0,%1,%2,%3};" \
        : "+f"((acc)[0]), "+f"((acc)[1]), "+f"((acc)[2]), "+f"((acc)[3]) \
        : "r"((a)[0]), "r"((a)[1]), "r"((a)[2]), "r"((a)[3]), \
          "r"(b0r), "r"(b1r))

#define LH_BLOCKS 32768   /* KC*D*64/256 */
#define XH_BLOCKS 512     /* 1024*512/4/256 */

// ---------------------------------------------------------------------------
// build_Lh v4 (+fused build_Xh): R9 store shape (8 e/thread, uint4 store),
// fast path = 8 unpredicated scalar loads when quad strictly below diagonal;
// slow path keeps per-element predicates (diag/zeros). Blocks beyond
// LH_BLOCKS convert X to fp16 (saves a launch).
// ---------------------------------------------------------------------------
__global__ void __launch_bounds__(256)
build_Lh(const float* __restrict__ diags, const float* __restrict__ lower,
         const float* __restrict__ X) {
    if (blockIdx.x >= LH_BLOCKS) {
        const int i = ((blockIdx.x - LH_BLOCKS) * 256 + threadIdx.x) * 4;
        float4 x = *(const float4*)&X[i];
        __half2 h0 = __floats2half2_rn(x.x, x.y);
        __half2 h1 = __floats2half2_rn(x.z, x.w);
        *(uint2*)((char*)g_Xh + i * 2) =
            make_uint2(*(uint32_t*)&h0, *(uint32_t*)&h1);
        return;
    }
    const size_t i = (size_t)blockIdx.x * 256 + threadIdx.x;  // KC*D*64
    const int ep = ((int)(i & 63)) << 3;         // e..e+7
    const size_t kd = i >> 6;                    // k*D + d
    const int d  = (int)(kd & 511);
    const int kk = (int)(kd >> 9);
    if (d < ((ep >> 7) << 7)) return;            // never-read region
    const float* rowp = lower + (size_t)kk * NLOW + (((size_t)d * (d - 1)) >> 1);
    float v[8];
    if (ep + 7 < d) {
        // fast path: all 8 strictly below the diagonal — no predication
#pragma unroll
        for (int t = 0; t < 8; ++t) v[t] = rowp[ep + t];
    } else {
#pragma unroll
        for (int t = 0; t < 8; ++t) {
            const int e = ep + t;
            v[t] = (e < d) ? rowp[e] : 0.f;
        }
        if (d >= ep && d < ep + 8) { float t = diags[kd]; v[d - ep] = t * t; }
    }
    uint4 u;
    __half2 h;
    h = __floats2half2_rn(v[0], v[1]); u.x = *(uint32_t*)&h;
    h = __floats2half2_rn(v[2], v[3]); u.y = *(uint32_t*)&h;
    h = __floats2half2_rn(v[4], v[5]); u.z = *(uint32_t*)&h;
    h = __floats2half2_rn(v[6], v[7]); u.w = *(uint32_t*)&h;
    *(uint4*)((char*)g_Lh + (kd * D + ep) * 2) = u;
}

// ---------------------------------------------------------------------------
__global__ void __launch_bounds__(512)
build_wL(const float* __restrict__ W) {
    __shared__ float ws[512];
    const int k = blockIdx.x, e = threadIdx.x;
    ws[e] = W[(size_t)k * D + e];
    __syncthreads();
    const __half* Lk = g_Lh + (size_t)k * D * D;
    float s = 0.f;
    const int dstart = (e >> 7) << 7;
#pragma unroll 4
    for (int d = dstart; d < D; ++d)
        s += ws[d] * __half2float(Lk[(size_t)d * D + e]);
    g_wL[(size_t)k * D + e] = s;
}

// ---------------------------------------------------------------------------
// Main GEMM: Q = Xh @ Lh block; epilogue squares (Q - wL[e]) and row-reduces.
// K-chunks of 64, 3 SMEM stages, one cp.async group per chunk, wait_group 1.
// A stage: 128x64 halfs stride 144 B; B stage: 64x128 halfs stride 272 B.
// Triangular skips: whole-chunk (n0=64, c=0) + fine-grained diagonal chunk
// (c == n0/64): keep only nt < 2ks+2 (B col-blocks at/below the diagonal).
// ---------------------------------------------------------------------------
#define ROFF   0
#define WLOFF  2048
#define STG0   2560
#define ASZ    18432                          /* 128 * 144 */
#define BSZ    17408                          /* 64 * 272 */
#define STGSZ  (ASZ + BSZ)                    /* 35840 */
#define SMEMSZ (2560 + 3 * 35840)             /* 110080 */

__global__ void __launch_bounds__(256, 2)
gml2_mma() {
    extern __shared__ char smem[];
    const int tid = threadIdx.x;
    const int wid = tid >> 5, lid = tid & 31;
    const int b0 = blockIdx.x * 128;
    const int k  = blockIdx.y;
    const int j  = blockIdx.z;
    const int e0 = j << 7;
    const int nc = 8 - (j << 1);              // K-chunks of 64: d in [e0, 512)

    const uint32_t sbase = smem_u32(smem);
    float* wLs = (float*)(smem + WLOFF);
    if (tid < 128) wLs[tid] = g_wL[(size_t)k * D + e0 + tid];

    const __half* Bk = g_Lh + (size_t)k * D * D;   // [d][e]
    const __half* Ab = g_Xh + (size_t)b0 * D;

#define ISSUE_CHUNK(cc, st) do {                                            \
        const int d0_ = e0 + (cc) * 64;                                     \
        const uint32_t as_ = sbase + STG0 + (st) * STGSZ;                   \
        const uint32_t bs_ = as_ + ASZ;                                     \
        _Pragma("unroll")                                                   \
        for (int it = 0; it < 4; ++it) {  /* A: 128 rows x 8 segs */        \
            const int idx = it * 256 + tid;                                 \
            const int row = idx >> 3, seg = idx & 7;                        \
            cpasync16(as_ + row * 144 + seg * 16,                           \
                      Ab + (size_t)row * D + d0_ + seg * 8);                \
        }                                                                   \
        _Pragma("unroll")                                                   \
        for (int it = 0; it < 4; ++it) {  /* B: 64 rows x 16 segs */        \
            const int idx = it * 256 + tid;                                 \
            const int rl = idx >> 4, seg = idx & 15;                        \
            cpasync16(bs_ + rl * 272 + seg * 16,                            \
                      Bk + (size_t)(d0_ + rl) * D + e0 + seg * 8);          \
        }                                                                   \
    } while (0)

    // ---- prologue: issue chunks 0,1
    ISSUE_CHUNK(0, 0);
    asm volatile("cp.async.commit_group;" ::: "memory");
    if (nc > 1) ISSUE_CHUNK(1, 1);
    asm volatile("cp.async.commit_group;" ::: "memory");

    float acc[2][8][4];
#pragma unroll
    for (int mt = 0; mt < 2; ++mt)
#pragma unroll
        for (int nt = 0; nt < 8; ++nt)
#pragma unroll
            for (int q = 0; q < 4; ++q) acc[mt][nt][q] = 0.f;

    const int m0 = (wid & 3) * 32, n0 = (wid >> 2) * 64;
    const int dc = n0 >> 6;                   // this warp's diagonal chunk
    const uint32_t aL = sbase + STG0 + (m0 + (lid & 15)) * 144 + (lid >> 4) * 16;
    const uint32_t bL = sbase + STG0 + ASZ +
                        (lid & 15) * 272 + (lid >> 4) * 16 + n0 * 2;

    int st = 0;
    for (int c = 0; c < nc; ++c) {
        asm volatile("cp.async.wait_group 1;" ::: "memory");
        __syncthreads();

        if (c + 2 < nc) {
            const int st2 = (st + 2 >= 3) ? st - 1 : st + 2;
            ISSUE_CHUNK(c + 2, st2);
        }
        asm volatile("cp.async.commit_group;" ::: "memory");

        const uint32_t aB = aL + st * STGSZ;
        const uint32_t bB = bL + st * STGSZ;

        if (c == dc) {
            // ---- diagonal chunk: cols strictly above diag are zero;
            //      keep nt < 2ks+2 only.
#pragma unroll
            for (int ks = 0; ks < 4; ++ks) {
                uint32_t a[2][4], b[8][2];
#pragma unroll
                for (int mt = 0; mt < 2; ++mt)
                    LDSM4(a[mt][0], a[mt][1], a[mt][2], a[mt][3],
                          aB + mt * (16 * 144) + ks * 32);
#pragma unroll
                for (int nt2 = 0; nt2 <= ks; ++nt2)
                    LDSM4T(b[nt2 * 2][0], b[nt2 * 2][1],
                           b[nt2 * 2 + 1][0], b[nt2 * 2 + 1][1],
                           bB + ks * (16 * 272) + nt2 * 32);
#pragma unroll
                for (int mt = 0; mt < 2; ++mt)
#pragma unroll
                    for (int nt = 0; nt < 8; ++nt)
                        if (nt < 2 * ks + 2)
                            HMMA(acc[mt][nt], a[mt], b[nt][0], b[nt][1]);
            }
        } else if (!(n0 == 64 && c == 0)) {
            // ---- full chunk
#pragma unroll
            for (int ks = 0; ks < 4; ++ks) {
                uint32_t a[2][4], b[8][2];
#pragma unroll
                for (int mt = 0; mt < 2; ++mt)
                    LDSM4(a[mt][0], a[mt][1], a[mt][2], a[mt][3],
                          aB + mt * (16 * 144) + ks * 32);
#pragma unroll
                for (int nt2 = 0; nt2 < 4; ++nt2)
                    LDSM4T(b[nt2 * 2][0], b[nt2 * 2][1],
                           b[nt2 * 2 + 1][0], b[nt2 * 2 + 1][1],
                           bB + ks * (16 * 272) + nt2 * 32);
#pragma unroll
                for (int mt = 0; mt < 2; ++mt)
#pragma unroll
                    for (int nt = 0; nt < 8; ++nt)
                        HMMA(acc[mt][nt], a[mt], b[nt][0], b[nt][1]);
            }
        }
        st = (st == 2) ? 0 : st + 1;
    }
#undef ISSUE_CHUNK

    // ---- epilogue: subtract wL, square, row-reduce
    const int gq = lid >> 2, tg = lid & 3;
    float q[4];
#pragma unroll
    for (int mt = 0; mt < 2; ++mt) {
        float s0 = 0.f, s1 = 0.f;
#pragma unroll
        for (int nt = 0; nt < 8; ++nt) {
            const int c0 = n0 + nt * 8 + tg * 2;
            const float wl0 = wLs[c0], wl1 = wLs[c0 + 1];
            float p0 = acc[mt][nt][0] - wl0;
            float p1 = acc[mt][nt][1] - wl1;
            float p2 = acc[mt][nt][2] - wl0;
            float p3 = acc[mt][nt][3] - wl1;
            s0 += p0 * p0 + p1 * p1;
            s1 += p2 * p2 + p3 * p3;
        }
        q[mt * 2 + 0] = s0;   // row m0 + 16*mt + gq
        q[mt * 2 + 1] = s1;   // row m0 + 16*mt + gq + 8
    }
#pragma unroll
    for (int i = 0; i < 4; ++i) {
        q[i] += __shfl_xor_sync(0xffffffffu, q[i], 1);
        q[i] += __shfl_xor_sync(0xffffffffu, q[i], 2);
    }
    float* red = (float*)(smem + ROFF);
    __syncthreads();
    if (tg == 0) {
        const int wn = wid >> 2;
        const int rr = m0 + gq;
        red[wn * 128 + rr +  0] = q[0];
        red[wn * 128 + rr +  8] = q[1];
        red[wn * 128 + rr + 16] = q[2];
        red[wn * 128 + rr + 24] = q[3];
    }
    __syncthreads();
    if (tid < 128) {
        float s = red[tid] + red[128 + tid];
        g_part[((size_t)j * 1024 + b0 + tid) * KC + k] = s;
    }
}

// ---------------------------------------------------------------------------
__global__ void finalize(float* __restrict__ out) {
    const size_t idx = (size_t)blockIdx.x * 256 + threadIdx.x;  // 1024*256
    float s = g_part[idx] + g_part[262144 + idx] +
              g_part[2 * 262144 + idx] + g_part[3 * 262144 + idx];
    out[idx] = sqrtf(s);
}

// ---------------------------------------------------------------------------
extern "C" void kernel_launch(void* const* d_in, const int* in_sizes, int n_in,
                              void* d_out, int out_size) {
    const float* X     = (const float*)d_in[0];  // [1024, 512]
    const float* W     = (const float*)d_in[1];  // [256, 1, 512]
    const float* diags = (const float*)d_in[2];  // [256, 512]
    const float* lower = (const float*)d_in[3];  // [256, 130816]
    float* out = (float*)d_out;                  // [1024, 256]

    build_Lh<<<LH_BLOCKS + XH_BLOCKS, 256>>>(diags, lower, X);
    build_wL<<<KC, 512>>>(W);

    cudaFuncSetAttribute(gml2_mma, cudaFuncAttributeMaxDynamicSharedMemorySize,
                         SMEMSZ);
    dim3 grid(8, KC, 4);
    gml2_mma<<<grid, 256, SMEMSZ>>>();

    finalize<<<1024, 256>>>(out);
}